// round 3
// baseline (speedup 1.0000x reference)
#include <cuda_runtime.h>
#include <cuda_bf16.h>
#include <cstdint>

#define N_NODES 20000
#define D_IN 512
#define D_OUT 64
#define N_EDGES 160000

// Scratch: buf0 holds h1 (post-prop1), then reused for h3 (post-prop2).
// buf1 holds h2 (post-GEMM1+relu).
__device__ float g_buf0[(size_t)N_NODES * D_IN];
__device__ float g_buf1[(size_t)N_NODES * D_IN];

// ---------------------------------------------------------------------------
// zero kernel (float4 grid-stride)
// ---------------------------------------------------------------------------
__global__ void zero_kernel(float4* p, int n4) {
    int i = blockIdx.x * blockDim.x + threadIdx.x;
    int stride = gridDim.x * blockDim.x;
    for (; i < n4; i += stride) p[i] = make_float4(0.f, 0.f, 0.f, 0.f);
}

// ---------------------------------------------------------------------------
// scatter-add propagate: out[dst] += x[src], one warp per edge, float4 atomics
// Indices are int32 (JAX downgrades int64 -> int32 without x64 enabled).
// ---------------------------------------------------------------------------
__global__ void scatter_add_kernel(const float* __restrict__ x,
                                   const int* __restrict__ src,
                                   const int* __restrict__ dst,
                                   float* __restrict__ out,
                                   int n_edges) {
    int warp = (blockIdx.x * blockDim.x + threadIdx.x) >> 5;
    int lane = threadIdx.x & 31;
    if (warp >= n_edges) return;
    int s = src[warp];
    int d = dst[warp];
    const float4* xs = reinterpret_cast<const float4*>(x + (size_t)s * D_IN);
    float4* od = reinterpret_cast<float4*>(out + (size_t)d * D_IN);
#pragma unroll
    for (int i = 0; i < (D_IN / 4) / 32; i++) {
        int idx = lane + i * 32;
        float4 v = xs[idx];
#if defined(__CUDA_ARCH__) && (__CUDA_ARCH__ >= 900)
        atomicAdd(&od[idx], v);
#else
        float* p = reinterpret_cast<float*>(&od[idx]);
        atomicAdd(p + 0, v.x);
        atomicAdd(p + 1, v.y);
        atomicAdd(p + 2, v.z);
        atomicAdd(p + 3, v.w);
#endif
    }
}

// ---------------------------------------------------------------------------
// Tiled SGEMM computing C[M,N] = A[M,K] * B[N,K]^T, optional fused ReLU.
// A row-major [M,K], B row-major [N,K] (so B rows are contiguous in K).
// ---------------------------------------------------------------------------
template <int BM, int BN, int BK, int TM, int TN, bool RELU>
__global__ void sgemm_bt_kernel(const float* __restrict__ A,
                                const float* __restrict__ B,
                                float* __restrict__ C,
                                int M, int N, int K) {
    constexpr int THREADS = (BM / TM) * (BN / TN);
    __shared__ float As[BK][BM];
    __shared__ float Bs[BK][BN];

    const int tid = threadIdx.x;
    const int m0 = blockIdx.y * BM;
    const int n0 = blockIdx.x * BN;

    const int tcol = tid % (BN / TN);
    const int trow = tid / (BN / TN);

    float acc[TM][TN];
#pragma unroll
    for (int i = 0; i < TM; i++)
#pragma unroll
        for (int j = 0; j < TN; j++) acc[i][j] = 0.f;

    constexpr int KV = BK / 4;           // float4s per row of a tile
    constexpr int A_F4 = BM * BK / 4;
    constexpr int B_F4 = BN * BK / 4;

    for (int k0 = 0; k0 < K; k0 += BK) {
        // load A tile (guard M), store transposed
#pragma unroll
        for (int i = tid; i < A_F4; i += THREADS) {
            int row = i / KV;
            int kc = (i % KV) * 4;
            float4 v = make_float4(0.f, 0.f, 0.f, 0.f);
            if (m0 + row < M)
                v = *reinterpret_cast<const float4*>(
                    &A[(size_t)(m0 + row) * K + k0 + kc]);
            As[kc + 0][row] = v.x;
            As[kc + 1][row] = v.y;
            As[kc + 2][row] = v.z;
            As[kc + 3][row] = v.w;
        }
        // load B tile (N is multiple of BN for our shapes)
#pragma unroll
        for (int i = tid; i < B_F4; i += THREADS) {
            int row = i / KV;
            int kc = (i % KV) * 4;
            float4 v = *reinterpret_cast<const float4*>(
                &B[(size_t)(n0 + row) * K + k0 + kc]);
            Bs[kc + 0][row] = v.x;
            Bs[kc + 1][row] = v.y;
            Bs[kc + 2][row] = v.z;
            Bs[kc + 3][row] = v.w;
        }
        __syncthreads();

#pragma unroll
        for (int k = 0; k < BK; k++) {
            float ra[TM], rb[TN];
#pragma unroll
            for (int i = 0; i < TM; i++) ra[i] = As[k][trow * TM + i];
#pragma unroll
            for (int j = 0; j < TN; j++) rb[j] = Bs[k][tcol * TN + j];
#pragma unroll
            for (int i = 0; i < TM; i++)
#pragma unroll
                for (int j = 0; j < TN; j++) acc[i][j] += ra[i] * rb[j];
        }
        __syncthreads();
    }

    // store (float4-vectorized, guard M)
#pragma unroll
    for (int i = 0; i < TM; i++) {
        int m = m0 + trow * TM + i;
        if (m >= M) continue;
#pragma unroll
        for (int j = 0; j < TN; j += 4) {
            float4 v;
            v.x = acc[i][j + 0];
            v.y = acc[i][j + 1];
            v.z = acc[i][j + 2];
            v.w = acc[i][j + 3];
            if (RELU) {
                v.x = fmaxf(v.x, 0.f);
                v.y = fmaxf(v.y, 0.f);
                v.z = fmaxf(v.z, 0.f);
                v.w = fmaxf(v.w, 0.f);
            }
            *reinterpret_cast<float4*>(&C[(size_t)m * N + n0 + tcol * TN + j]) = v;
        }
    }
}

// ---------------------------------------------------------------------------
// log_softmax in-place over rows of 64, one warp per row (2 elems/lane)
// ---------------------------------------------------------------------------
__global__ void log_softmax_kernel(float* __restrict__ out, int M) {
    int row = blockIdx.x * (blockDim.x >> 5) + (threadIdx.x >> 5);
    int lane = threadIdx.x & 31;
    if (row >= M) return;
    float* p = out + (size_t)row * D_OUT;
    float a = p[lane];
    float b = p[lane + 32];
    float mx = fmaxf(a, b);
#pragma unroll
    for (int off = 16; off > 0; off >>= 1)
        mx = fmaxf(mx, __shfl_xor_sync(0xffffffffu, mx, off));
    float s = expf(a - mx) + expf(b - mx);
#pragma unroll
    for (int off = 16; off > 0; off >>= 1)
        s += __shfl_xor_sync(0xffffffffu, s, off);
    float l = mx + logf(s);
    p[lane] = a - l;
    p[lane + 32] = b - l;
}

// ---------------------------------------------------------------------------
// launch
// ---------------------------------------------------------------------------
extern "C" void kernel_launch(void* const* d_in, const int* in_sizes, int n_in,
                              void* d_out, int out_size) {
    const float* x = (const float*)d_in[0];
    const int* ei = (const int*)d_in[1];
    const float* W1 = (const float*)d_in[2];
    const float* W2 = (const float*)d_in[3];
    float* out = (float*)d_out;

    const int* src = ei;
    const int* dst = ei + N_EDGES;

    float* h1;  // also h3
    float* h2;
    cudaGetSymbolAddress((void**)&h1, g_buf0);
    cudaGetSymbolAddress((void**)&h2, g_buf1);

    const int n4 = (N_NODES * D_IN) / 4;           // 2,560,000
    const int zero_blocks = (n4 + 255) / 256;
    const int scat_blocks = (N_EDGES * 32 + 255) / 256;  // warp per edge

    // --- propagate 1: h1 = segment_sum(x[src] -> dst) ---
    zero_kernel<<<zero_blocks, 256>>>((float4*)h1, n4);
    scatter_add_kernel<<<scat_blocks, 256>>>(x, src, dst, h1, N_EDGES);

    // --- GEMM1 + ReLU: h2 = relu(h1 @ W1^T)  [20000,512] ---
    {
        dim3 grid(D_IN / 128, (N_NODES + 127) / 128);
        sgemm_bt_kernel<128, 128, 8, 8, 8, true>
            <<<grid, 256>>>(h1, W1, h2, N_NODES, D_IN, D_IN);
    }

    // --- propagate 2: h3(=h1 buffer) = segment_sum(h2[src] -> dst) ---
    zero_kernel<<<zero_blocks, 256>>>((float4*)h1, n4);
    scatter_add_kernel<<<scat_blocks, 256>>>(h2, src, dst, h1, N_EDGES);

    // --- GEMM2: out = h3 @ W2^T  [20000,64] ---
    {
        dim3 grid(D_OUT / 64, (N_NODES + 127) / 128);
        sgemm_bt_kernel<128, 64, 8, 8, 4, false>
            <<<grid, 256>>>(h1, W2, out, N_NODES, D_OUT, D_IN);
    }

    // --- log_softmax in-place ---
    {
        int blocks = (N_NODES + 7) / 8;  // 8 warps/block
        log_softmax_kernel<<<blocks, 256>>>(out, N_NODES);
    }
}

// round 4
// speedup vs baseline: 1.0731x; 1.0731x over previous
#include <cuda_runtime.h>
#include <cuda_bf16.h>
#include <cstdint>

#define N_NODES 20000
#define D_IN 512
#define D_OUT 64
#define N_EDGES 160000

// h buffers: g_buf0 = h1 (post-prop1) then h3 (post-prop2); g_buf1 = h2.
__device__ float g_buf0[(size_t)N_NODES * D_IN];
__device__ float g_buf1[(size_t)N_NODES * D_IN];

// CSR-by-destination scratch
__device__ int g_deg[N_NODES];
__device__ int g_off[N_NODES + 1];
__device__ int g_cursor[N_NODES];
__device__ int g_adj[N_EDGES];   // src node of each incoming edge, grouped by dst

// ---------------------------------------------------------------------------
// CSR build kernels
// ---------------------------------------------------------------------------
__global__ void csr_zero_deg(int* deg) {
    int i = blockIdx.x * blockDim.x + threadIdx.x;
    if (i < N_NODES) deg[i] = 0;
}

__global__ void csr_hist(const int* __restrict__ dst, int* __restrict__ deg) {
    int e = blockIdx.x * blockDim.x + threadIdx.x;
    if (e < N_EDGES) atomicAdd(&deg[dst[e]], 1);
}

// Single-block exclusive scan of 20000 ints (1024 threads x 20 items each).
__global__ void csr_scan(const int* __restrict__ deg, int* __restrict__ off,
                         int* __restrict__ cursor) {
    __shared__ int ssum[1024];
    const int t = threadIdx.x;
    const int ITEMS = 20;  // 1024*20 = 20480 >= 20000
    int base = t * ITEMS;
    int local[ITEMS];
    int s = 0;
#pragma unroll
    for (int i = 0; i < ITEMS; i++) {
        int idx = base + i;
        int v = (idx < N_NODES) ? deg[idx] : 0;
        local[i] = s;
        s += v;
    }
    ssum[t] = s;
    __syncthreads();
    // Hillis-Steele inclusive scan over 1024 partial sums
    for (int d = 1; d < 1024; d <<= 1) {
        int v = (t >= d) ? ssum[t - d] : 0;
        __syncthreads();
        ssum[t] += v;
        __syncthreads();
    }
    int prev = (t > 0) ? ssum[t - 1] : 0;
#pragma unroll
    for (int i = 0; i < ITEMS; i++) {
        int idx = base + i;
        if (idx < N_NODES) {
            int o = prev + local[i];
            off[idx] = o;
            cursor[idx] = o;
        }
    }
    if (t == 1023) off[N_NODES] = ssum[1023];
}

__global__ void csr_fill(const int* __restrict__ src, const int* __restrict__ dst,
                         int* __restrict__ cursor, int* __restrict__ adj) {
    int e = blockIdx.x * blockDim.x + threadIdx.x;
    if (e < N_EDGES) {
        int p = atomicAdd(&cursor[dst[e]], 1);
        adj[p] = src[e];
    }
}

// ---------------------------------------------------------------------------
// Gather propagate: out[n] = sum over incoming edges of x[adj[i]].
// One 128-thread block per node; each thread owns one float4 (512 floats).
// No atomics, no pre-zeroing (every row written exactly once).
// ---------------------------------------------------------------------------
__global__ void gather_prop(const float* __restrict__ x,
                            const int* __restrict__ off,
                            const int* __restrict__ adj,
                            float* __restrict__ out) {
    const int node = blockIdx.x;
    const int t = threadIdx.x;  // 0..127
    int b = off[node];
    int e = off[node + 1];
    float4 acc = make_float4(0.f, 0.f, 0.f, 0.f);
    int i = b;
    for (; i + 1 < e; i += 2) {
        int s0 = adj[i];
        int s1 = adj[i + 1];
        float4 v0 = reinterpret_cast<const float4*>(x + (size_t)s0 * D_IN)[t];
        float4 v1 = reinterpret_cast<const float4*>(x + (size_t)s1 * D_IN)[t];
        acc.x += v0.x + v1.x;
        acc.y += v0.y + v1.y;
        acc.z += v0.z + v1.z;
        acc.w += v0.w + v1.w;
    }
    if (i < e) {
        int s0 = adj[i];
        float4 v0 = reinterpret_cast<const float4*>(x + (size_t)s0 * D_IN)[t];
        acc.x += v0.x;
        acc.y += v0.y;
        acc.z += v0.z;
        acc.w += v0.w;
    }
    reinterpret_cast<float4*>(out + (size_t)node * D_IN)[t] = acc;
}

// ---------------------------------------------------------------------------
// Tiled SGEMM computing C[M,N] = A[M,K] * B[N,K]^T, optional fused ReLU.
// ---------------------------------------------------------------------------
template <int BM, int BN, int BK, int TM, int TN, bool RELU>
__global__ void sgemm_bt_kernel(const float* __restrict__ A,
                                const float* __restrict__ B,
                                float* __restrict__ C,
                                int M, int N, int K) {
    constexpr int THREADS = (BM / TM) * (BN / TN);
    __shared__ float As[BK][BM];
    __shared__ float Bs[BK][BN];

    const int tid = threadIdx.x;
    const int m0 = blockIdx.y * BM;
    const int n0 = blockIdx.x * BN;

    const int tcol = tid % (BN / TN);
    const int trow = tid / (BN / TN);

    float acc[TM][TN];
#pragma unroll
    for (int i = 0; i < TM; i++)
#pragma unroll
        for (int j = 0; j < TN; j++) acc[i][j] = 0.f;

    constexpr int KV = BK / 4;
    constexpr int A_F4 = BM * BK / 4;
    constexpr int B_F4 = BN * BK / 4;

    for (int k0 = 0; k0 < K; k0 += BK) {
#pragma unroll
        for (int i = tid; i < A_F4; i += THREADS) {
            int row = i / KV;
            int kc = (i % KV) * 4;
            float4 v = make_float4(0.f, 0.f, 0.f, 0.f);
            if (m0 + row < M)
                v = *reinterpret_cast<const float4*>(
                    &A[(size_t)(m0 + row) * K + k0 + kc]);
            As[kc + 0][row] = v.x;
            As[kc + 1][row] = v.y;
            As[kc + 2][row] = v.z;
            As[kc + 3][row] = v.w;
        }
#pragma unroll
        for (int i = tid; i < B_F4; i += THREADS) {
            int row = i / KV;
            int kc = (i % KV) * 4;
            float4 v = *reinterpret_cast<const float4*>(
                &B[(size_t)(n0 + row) * K + k0 + kc]);
            Bs[kc + 0][row] = v.x;
            Bs[kc + 1][row] = v.y;
            Bs[kc + 2][row] = v.z;
            Bs[kc + 3][row] = v.w;
        }
        __syncthreads();

#pragma unroll
        for (int k = 0; k < BK; k++) {
            float ra[TM], rb[TN];
#pragma unroll
            for (int i = 0; i < TM; i++) ra[i] = As[k][trow * TM + i];
#pragma unroll
            for (int j = 0; j < TN; j++) rb[j] = Bs[k][tcol * TN + j];
#pragma unroll
            for (int i = 0; i < TM; i++)
#pragma unroll
                for (int j = 0; j < TN; j++) acc[i][j] += ra[i] * rb[j];
        }
        __syncthreads();
    }

#pragma unroll
    for (int i = 0; i < TM; i++) {
        int m = m0 + trow * TM + i;
        if (m >= M) continue;
#pragma unroll
        for (int j = 0; j < TN; j += 4) {
            float4 v;
            v.x = acc[i][j + 0];
            v.y = acc[i][j + 1];
            v.z = acc[i][j + 2];
            v.w = acc[i][j + 3];
            if (RELU) {
                v.x = fmaxf(v.x, 0.f);
                v.y = fmaxf(v.y, 0.f);
                v.z = fmaxf(v.z, 0.f);
                v.w = fmaxf(v.w, 0.f);
            }
            *reinterpret_cast<float4*>(&C[(size_t)m * N + n0 + tcol * TN + j]) = v;
        }
    }
}

// ---------------------------------------------------------------------------
// log_softmax in-place over rows of 64, one warp per row (2 elems/lane)
// ---------------------------------------------------------------------------
__global__ void log_softmax_kernel(float* __restrict__ out, int M) {
    int row = blockIdx.x * (blockDim.x >> 5) + (threadIdx.x >> 5);
    int lane = threadIdx.x & 31;
    if (row >= M) return;
    float* p = out + (size_t)row * D_OUT;
    float a = p[lane];
    float b = p[lane + 32];
    float mx = fmaxf(a, b);
#pragma unroll
    for (int off = 16; off > 0; off >>= 1)
        mx = fmaxf(mx, __shfl_xor_sync(0xffffffffu, mx, off));
    float s = expf(a - mx) + expf(b - mx);
#pragma unroll
    for (int off = 16; off > 0; off >>= 1)
        s += __shfl_xor_sync(0xffffffffu, s, off);
    float l = mx + logf(s);
    p[lane] = a - l;
    p[lane + 32] = b - l;
}

// ---------------------------------------------------------------------------
// launch
// ---------------------------------------------------------------------------
extern "C" void kernel_launch(void* const* d_in, const int* in_sizes, int n_in,
                              void* d_out, int out_size) {
    const float* x = (const float*)d_in[0];
    const int* ei = (const int*)d_in[1];
    const float* W1 = (const float*)d_in[2];
    const float* W2 = (const float*)d_in[3];
    float* out = (float*)d_out;

    const int* src = ei;
    const int* dst = ei + N_EDGES;

    float* h1;
    float* h2;
    int *deg, *off, *cursor, *adj;
    cudaGetSymbolAddress((void**)&h1, g_buf0);
    cudaGetSymbolAddress((void**)&h2, g_buf1);
    cudaGetSymbolAddress((void**)&deg, g_deg);
    cudaGetSymbolAddress((void**)&off, g_off);
    cudaGetSymbolAddress((void**)&cursor, g_cursor);
    cudaGetSymbolAddress((void**)&adj, g_adj);

    // --- CSR build (by destination) ---
    csr_zero_deg<<<(N_NODES + 255) / 256, 256>>>(deg);
    csr_hist<<<(N_EDGES + 255) / 256, 256>>>(dst, deg);
    csr_scan<<<1, 1024>>>(deg, off, cursor);
    csr_fill<<<(N_EDGES + 255) / 256, 256>>>(src, dst, cursor, adj);

    // --- propagate 1: h1 = segment_sum(x[src] -> dst) ---
    gather_prop<<<N_NODES, 128>>>(x, off, adj, h1);

    // --- GEMM1 + ReLU: h2 = relu(h1 @ W1^T) ---
    {
        dim3 grid(D_IN / 128, (N_NODES + 127) / 128);
        sgemm_bt_kernel<128, 128, 16, 8, 8, true>
            <<<grid, 256>>>(h1, W1, h2, N_NODES, D_IN, D_IN);
    }

    // --- propagate 2: h3(=h1) = segment_sum(h2[src] -> dst) ---
    gather_prop<<<N_NODES, 128>>>(h2, off, adj, h1);

    // --- GEMM2: out = h3 @ W2^T ---
    {
        dim3 grid(D_OUT / 64, (N_NODES + 127) / 128);
        sgemm_bt_kernel<128, 64, 16, 8, 4, false>
            <<<grid, 256>>>(h1, W2, out, N_NODES, D_OUT, D_IN);
    }

    // --- log_softmax in-place ---
    log_softmax_kernel<<<(N_NODES + 7) / 8, 256>>>(out, N_NODES);
}

// round 6
// speedup vs baseline: 2.0000x; 1.8638x over previous
#include <cuda_runtime.h>
#include <cuda_bf16.h>
#include <cstdint>

#define N_NODES 20000
#define D_IN 512
#define D_OUT 64
#define N_EDGES 160000

// ---------------------------------------------------------------------------
// device globals (no allocation allowed)
// ---------------------------------------------------------------------------
__device__ float g_buf0[(size_t)N_NODES * D_IN];   // h1 / h3
__device__ float g_buf1[(size_t)N_NODES * D_IN];   // h2
__device__ int g_deg[N_NODES];
__device__ int g_off[N_NODES + 1];
__device__ int g_cursor[N_NODES];
__device__ int g_adj[N_EDGES];
__device__ __nv_bfloat16 g_w1_hi[D_IN * D_IN];
__device__ __nv_bfloat16 g_w1_lo[D_IN * D_IN];
__device__ __nv_bfloat16 g_w2_hi[D_OUT * D_IN];
__device__ __nv_bfloat16 g_w2_lo[D_OUT * D_IN];

// ---------------------------------------------------------------------------
// CSR build
// ---------------------------------------------------------------------------
__global__ void csr_zero_deg(int* deg) {
    int i = blockIdx.x * blockDim.x + threadIdx.x;
    if (i < N_NODES) deg[i] = 0;
}
__global__ void csr_hist(const int* __restrict__ dst, int* __restrict__ deg) {
    int e = blockIdx.x * blockDim.x + threadIdx.x;
    if (e < N_EDGES) atomicAdd(&deg[dst[e]], 1);
}
__global__ void csr_scan(const int* __restrict__ deg, int* __restrict__ off,
                         int* __restrict__ cursor) {
    __shared__ int ssum[1024];
    const int t = threadIdx.x;
    const int ITEMS = 20;
    int base = t * ITEMS;
    int local[ITEMS];
    int s = 0;
#pragma unroll
    for (int i = 0; i < ITEMS; i++) {
        int idx = base + i;
        int v = (idx < N_NODES) ? deg[idx] : 0;
        local[i] = s;
        s += v;
    }
    ssum[t] = s;
    __syncthreads();
    for (int d = 1; d < 1024; d <<= 1) {
        int v = (t >= d) ? ssum[t - d] : 0;
        __syncthreads();
        ssum[t] += v;
        __syncthreads();
    }
    int prev = (t > 0) ? ssum[t - 1] : 0;
#pragma unroll
    for (int i = 0; i < ITEMS; i++) {
        int idx = base + i;
        if (idx < N_NODES) {
            int o = prev + local[i];
            off[idx] = o;
            cursor[idx] = o;
        }
    }
    if (t == 1023) off[N_NODES] = ssum[1023];
}
__global__ void csr_fill(const int* __restrict__ src, const int* __restrict__ dst,
                         int* __restrict__ cursor, int* __restrict__ adj) {
    int e = blockIdx.x * blockDim.x + threadIdx.x;
    if (e < N_EDGES) {
        int p = atomicAdd(&cursor[dst[e]], 1);
        adj[p] = src[e];
    }
}

// ---------------------------------------------------------------------------
// Gather propagate (one block of 128 per node, float4 per thread)
// ---------------------------------------------------------------------------
__global__ void gather_prop(const float* __restrict__ x,
                            const int* __restrict__ off,
                            const int* __restrict__ adj,
                            float* __restrict__ out) {
    const int node = blockIdx.x;
    const int t = threadIdx.x;
    int b = off[node];
    int e = off[node + 1];
    float4 acc = make_float4(0.f, 0.f, 0.f, 0.f);
    int i = b;
    for (; i + 1 < e; i += 2) {
        int s0 = adj[i];
        int s1 = adj[i + 1];
        float4 v0 = reinterpret_cast<const float4*>(x + (size_t)s0 * D_IN)[t];
        float4 v1 = reinterpret_cast<const float4*>(x + (size_t)s1 * D_IN)[t];
        acc.x += v0.x + v1.x;
        acc.y += v0.y + v1.y;
        acc.z += v0.z + v1.z;
        acc.w += v0.w + v1.w;
    }
    if (i < e) {
        int s0 = adj[i];
        float4 v0 = reinterpret_cast<const float4*>(x + (size_t)s0 * D_IN)[t];
        acc.x += v0.x;
        acc.y += v0.y;
        acc.z += v0.z;
        acc.w += v0.w;
    }
    reinterpret_cast<float4*>(out + (size_t)node * D_IN)[t] = acc;
}

// ---------------------------------------------------------------------------
// Split fp32 weight matrix into bf16 hi/lo
// ---------------------------------------------------------------------------
__global__ void split_w(const float* __restrict__ w, __nv_bfloat16* __restrict__ hi,
                        __nv_bfloat16* __restrict__ lo, int n) {
    int i = blockIdx.x * blockDim.x + threadIdx.x;
    if (i < n) {
        float a = w[i];
        __nv_bfloat16 h = __float2bfloat16_rn(a);
        hi[i] = h;
        lo[i] = __float2bfloat16_rn(a - __bfloat162float(h));
    }
}

// ---------------------------------------------------------------------------
// mma.sync helpers
// ---------------------------------------------------------------------------
__device__ __forceinline__ void mma_bf16(float* d, const uint32_t* a,
                                         const uint32_t* b) {
    asm volatile(
        "mma.sync.aligned.m16n8k16.row.col.f32.bf16.bf16.f32 "
        "{%0,%1,%2,%3}, {%4,%5,%6,%7}, {%8,%9}, {%0,%1,%2,%3};"
        : "+f"(d[0]), "+f"(d[1]), "+f"(d[2]), "+f"(d[3])
        : "r"(a[0]), "r"(a[1]), "r"(a[2]), "r"(a[3]), "r"(b[0]), "r"(b[1]));
}

__device__ __forceinline__ void ldmx4(uint32_t* r, uint32_t addr) {
    asm volatile(
        "ldmatrix.sync.aligned.m8n8.x4.shared.b16 {%0,%1,%2,%3}, [%4];"
        : "=r"(r[0]), "=r"(r[1]), "=r"(r[2]), "=r"(r[3])
        : "r"(addr));
}

// ---------------------------------------------------------------------------
// Split-bf16 GEMM via mma.sync: C[M,N] = A[M,512] * B[N,512]^T
// A fp32 (converted to hi/lo bf16 inline), B pre-split bf16 hi/lo.
// CTA tile 128x64, BK=32, 8 warps each computing a 32x32 tile.
// smem rows padded to 80B -> conflict-free ldmatrix.
// ---------------------------------------------------------------------------
#define LDS_STRIDE 80
#define SM_AH 0
#define SM_AL (128 * LDS_STRIDE)            // 10240
#define SM_BH (2 * 128 * LDS_STRIDE)        // 20480
#define SM_BL (2 * 128 * LDS_STRIDE + 64 * LDS_STRIDE)  // 25600
#define SM_TOTAL (2 * 128 * LDS_STRIDE + 2 * 64 * LDS_STRIDE)  // 30720

template <bool RELU>
__global__ __launch_bounds__(256)
void gemm_mma(const float* __restrict__ A,
              const __nv_bfloat16* __restrict__ Bh,
              const __nv_bfloat16* __restrict__ Bl,
              float* __restrict__ C, int M, int N) {
    __shared__ __align__(16) char smem[SM_TOTAL];
    const int tid = threadIdx.x;
    const int lane = tid & 31;
    const int wid = tid >> 5;
    const int wm = wid & 3;        // 4 row-blocks of 32
    const int wn = wid >> 2;       // 2 col-blocks of 32
    const int m0 = blockIdx.x * 128;
    const int n0 = blockIdx.y * 64;

    const uint32_t sb = (uint32_t)__cvta_generic_to_shared(smem);

    float acc[2][4][4];
#pragma unroll
    for (int i = 0; i < 2; i++)
#pragma unroll
        for (int j = 0; j < 4; j++)
#pragma unroll
            for (int k = 0; k < 4; k++) acc[i][j][k] = 0.f;

    // A load mapping: row = tid/2 (0..127), half = tid%2 (16 floats each)
    const int ar = tid >> 1;
    const int ah = tid & 1;
    const bool arow_ok = (m0 + ar) < M;
    // B load mapping: row = tid/4 (0..63), q = tid%4 (8 bf16 each)
    const int br = tid >> 2;
    const int bq = tid & 3;

    // ldmatrix base addresses (within tile; add hi/lo region offset per use)
    const uint32_t a_lm = sb + (uint32_t)((wm * 32 + (lane & 15)) * LDS_STRIDE +
                                          (lane >> 4) * 16);
    const uint32_t b_lm = sb + SM_BH + (uint32_t)((wn * 32 + (lane & 15)) * LDS_STRIDE +
                                                  (lane >> 4) * 16);

    for (int kc = 0; kc < 16; kc++) {
        // ---- load A fp32, convert to bf16 hi/lo, store to smem ----
        float4 av[4];
        if (arow_ok) {
            const float4* ap = reinterpret_cast<const float4*>(
                A + (size_t)(m0 + ar) * D_IN + kc * 32 + ah * 16);
#pragma unroll
            for (int i = 0; i < 4; i++) av[i] = ap[i];
        } else {
#pragma unroll
            for (int i = 0; i < 4; i++) av[i] = make_float4(0.f, 0.f, 0.f, 0.f);
        }
        // B (bf16 pre-split): 16B each
        const uint4 bhv = *reinterpret_cast<const uint4*>(
            Bh + (size_t)(n0 + br) * D_IN + kc * 32 + bq * 8);
        const uint4 blv = *reinterpret_cast<const uint4*>(
            Bl + (size_t)(n0 + br) * D_IN + kc * 32 + bq * 8);

        __syncthreads();

        {
            union { __nv_bfloat162 h2[8]; uint4 u[2]; } hi, lo;
            const float* f = reinterpret_cast<const float*>(av);
#pragma unroll
            for (int j = 0; j < 8; j++) {
                float a0 = f[2 * j], a1 = f[2 * j + 1];
                __nv_bfloat16 h0 = __float2bfloat16_rn(a0);
                __nv_bfloat16 h1 = __float2bfloat16_rn(a1);
                hi.h2[j] = __halves2bfloat162(h0, h1);
                lo.h2[j] = __halves2bfloat162(
                    __float2bfloat16_rn(a0 - __bfloat162float(h0)),
                    __float2bfloat16_rn(a1 - __bfloat162float(h1)));
            }
            char* pa = smem + ar * LDS_STRIDE + ah * 32;
            *reinterpret_cast<uint4*>(pa + SM_AH) = hi.u[0];
            *reinterpret_cast<uint4*>(pa + SM_AH + 16) = hi.u[1];
            *reinterpret_cast<uint4*>(pa + SM_AL) = lo.u[0];
            *reinterpret_cast<uint4*>(pa + SM_AL + 16) = lo.u[1];
        }
        {
            char* pb = smem + br * LDS_STRIDE + bq * 16;
            *reinterpret_cast<uint4*>(pb + SM_BH) = bhv;
            *reinterpret_cast<uint4*>(pb + SM_BL) = blv;
        }
        __syncthreads();

        // ---- compute: 2 ksteps of 16 ----
#pragma unroll
        for (int ks = 0; ks < 2; ks++) {
            uint32_t aH[2][4], aL[2][4], bH[2][4], bL[2][4];
#pragma unroll
            for (int mi = 0; mi < 2; mi++) {
                uint32_t addr = a_lm + mi * 16 * LDS_STRIDE + ks * 32;
                ldmx4(aH[mi], addr);
                ldmx4(aL[mi], addr + (SM_AL - SM_AH));
            }
#pragma unroll
            for (int ng = 0; ng < 2; ng++) {
                uint32_t addr = b_lm + ng * 16 * LDS_STRIDE + ks * 32;
                ldmx4(bH[ng], addr);
                ldmx4(bL[ng], addr + (SM_BL - SM_BH));
            }
#pragma unroll
            for (int mi = 0; mi < 2; mi++) {
#pragma unroll
                for (int ng = 0; ng < 2; ng++) {
#pragma unroll
                    for (int nb = 0; nb < 2; nb++) {
                        int ni = ng * 2 + nb;
                        uint32_t bh2[2] = {bH[ng][nb], bH[ng][nb + 2]};
                        uint32_t bl2[2] = {bL[ng][nb], bL[ng][nb + 2]};
                        mma_bf16(acc[mi][ni], aH[mi], bh2);
                        mma_bf16(acc[mi][ni], aH[mi], bl2);
                        mma_bf16(acc[mi][ni], aL[mi], bh2);
                    }
                }
            }
        }
    }

    // ---- epilogue ----
    const int g = lane >> 2;
    const int t4 = lane & 3;
#pragma unroll
    for (int mi = 0; mi < 2; mi++) {
#pragma unroll
        for (int ni = 0; ni < 4; ni++) {
            int col = n0 + wn * 32 + ni * 8 + t4 * 2;
            int row0 = m0 + wm * 32 + mi * 16 + g;
            int row1 = row0 + 8;
            float2 v0 = make_float2(acc[mi][ni][0], acc[mi][ni][1]);
            float2 v1 = make_float2(acc[mi][ni][2], acc[mi][ni][3]);
            if (RELU) {
                v0.x = fmaxf(v0.x, 0.f); v0.y = fmaxf(v0.y, 0.f);
                v1.x = fmaxf(v1.x, 0.f); v1.y = fmaxf(v1.y, 0.f);
            }
            if (row0 < M)
                *reinterpret_cast<float2*>(C + (size_t)row0 * N + col) = v0;
            if (row1 < M)
                *reinterpret_cast<float2*>(C + (size_t)row1 * N + col) = v1;
        }
    }
}

// ---------------------------------------------------------------------------
// log_softmax in-place over rows of 64, one warp per row (2 elems/lane)
// ---------------------------------------------------------------------------
__global__ void log_softmax_kernel(float* __restrict__ out, int M) {
    int row = blockIdx.x * (blockDim.x >> 5) + (threadIdx.x >> 5);
    int lane = threadIdx.x & 31;
    if (row >= M) return;
    float* p = out + (size_t)row * D_OUT;
    float a = p[lane];
    float b = p[lane + 32];
    float mx = fmaxf(a, b);
#pragma unroll
    for (int off = 16; off > 0; off >>= 1)
        mx = fmaxf(mx, __shfl_xor_sync(0xffffffffu, mx, off));
    float s = expf(a - mx) + expf(b - mx);
#pragma unroll
    for (int off = 16; off > 0; off >>= 1)
        s += __shfl_xor_sync(0xffffffffu, s, off);
    float l = mx + logf(s);
    p[lane] = a - l;
    p[lane + 32] = b - l;
}

// ---------------------------------------------------------------------------
// launch
// ---------------------------------------------------------------------------
extern "C" void kernel_launch(void* const* d_in, const int* in_sizes, int n_in,
                              void* d_out, int out_size) {
    const float* x = (const float*)d_in[0];
    const int* ei = (const int*)d_in[1];
    const float* W1 = (const float*)d_in[2];
    const float* W2 = (const float*)d_in[3];
    float* out = (float*)d_out;

    const int* src = ei;
    const int* dst = ei + N_EDGES;

    float *h1, *h2;
    int *deg, *off, *cursor, *adj;
    __nv_bfloat16 *w1h, *w1l, *w2h, *w2l;
    cudaGetSymbolAddress((void**)&h1, g_buf0);
    cudaGetSymbolAddress((void**)&h2, g_buf1);
    cudaGetSymbolAddress((void**)&deg, g_deg);
    cudaGetSymbolAddress((void**)&off, g_off);
    cudaGetSymbolAddress((void**)&cursor, g_cursor);
    cudaGetSymbolAddress((void**)&adj, g_adj);
    cudaGetSymbolAddress((void**)&w1h, g_w1_hi);
    cudaGetSymbolAddress((void**)&w1l, g_w1_lo);
    cudaGetSymbolAddress((void**)&w2h, g_w2_hi);
    cudaGetSymbolAddress((void**)&w2l, g_w2_lo);

    // weight split (cheap, independent)
    split_w<<<(D_IN * D_IN + 255) / 256, 256>>>(W1, w1h, w1l, D_IN * D_IN);
    split_w<<<(D_OUT * D_IN + 255) / 256, 256>>>(W2, w2h, w2l, D_OUT * D_IN);

    // CSR build (by destination)
    csr_zero_deg<<<(N_NODES + 255) / 256, 256>>>(deg);
    csr_hist<<<(N_EDGES + 255) / 256, 256>>>(dst, deg);
    csr_scan<<<1, 1024>>>(deg, off, cursor);
    csr_fill<<<(N_EDGES + 255) / 256, 256>>>(src, dst, cursor, adj);

    const int n_mtiles = (N_NODES + 127) / 128;  // 157

    // propagate 1: h1 = segment_sum(x[src] -> dst)
    gather_prop<<<N_NODES, 128>>>(x, off, adj, h1);

    // GEMM1 + ReLU: h2 = relu(h1 @ W1^T)
    {
        dim3 grid(n_mtiles, D_IN / 64);
        gemm_mma<true><<<grid, 256>>>(h1, w1h, w1l, h2, N_NODES, D_IN);
    }

    // propagate 2: h3(=h1) = segment_sum(h2[src] -> dst)
    gather_prop<<<N_NODES, 128>>>(h2, off, adj, h1);

    // GEMM2: out = h3 @ W2^T
    {
        dim3 grid(n_mtiles, 1);
        gemm_mma<false><<<grid, 256>>>(h1, w2h, w2l, out, N_NODES, D_OUT);
    }

    // log_softmax in-place
    log_softmax_kernel<<<(N_NODES + 7) / 8, 256>>>(out, N_NODES);
}